// round 14
// baseline (speedup 1.0000x reference)
#include <cuda_runtime.h>
#include <cuda_fp16.h>
#include <cstdint>

#define NB  16
#define NC  512
#define NK  512
#define NHW 4096
#define NP  (NB * NHW)   // 65536 pixels

#define RESCUE_T 0.2f

// --------------------------------------------------------------------------
// Allocation-free scratch
// --------------------------------------------------------------------------
__device__ __half g_c16[NK * NC];           // centers fp16 [k][c]
__device__ float  g_centT[NC * NK];         // centers fp32 transposed [c][k]
__device__ float  g_csq[NK];
__device__ unsigned long long g_partk[(size_t)NP * 4];
__device__ float              g_partv[(size_t)NP * 4];
__device__ int g_count;
__device__ int g_queue[NP];

// --------------------------------------------------------------------------
// Helpers
// --------------------------------------------------------------------------
__device__ __forceinline__ uint32_t smem_u32(const void* p) {
    uint32_t a;
    asm("{ .reg .u64 t; cvta.to.shared.u64 t, %1; cvt.u32.u64 %0, t; }"
        : "=r"(a) : "l"(p));
    return a;
}
__device__ __forceinline__ unsigned long long enc_key(float v, int k) {
    unsigned u = __float_as_uint(v);
    u = (u & 0x80000000u) ? ~u : (u | 0x80000000u);
    return ((unsigned long long)u << 32) | (unsigned)k;
}
__device__ __forceinline__ float key_val(unsigned long long key) {
    unsigned u = (unsigned)(key >> 32);
    unsigned b = (u & 0x80000000u) ? (u & 0x7FFFFFFFu) : ~u;
    return __uint_as_float(b);
}
__device__ __forceinline__ void t2merge(unsigned long long& k1, float& v2,
                                        unsigned long long ok1, float ov2) {
    if (ok1 < k1) { v2 = fminf(key_val(k1), ov2); k1 = ok1; }
    else          { v2 = fminf(v2, key_val(ok1)); }
}
__device__ __forceinline__ void ldmx4(uint32_t* r, uint32_t addr) {
    asm volatile("ldmatrix.sync.aligned.m8n8.x4.shared.b16 {%0,%1,%2,%3}, [%4];"
                 : "=r"(r[0]), "=r"(r[1]), "=r"(r[2]), "=r"(r[3]) : "r"(addr));
}
__device__ __forceinline__ void ldmx4t(uint32_t* r, uint32_t addr) {
    asm volatile("ldmatrix.sync.aligned.m8n8.x4.trans.shared.b16 {%0,%1,%2,%3}, [%4];"
                 : "=r"(r[0]), "=r"(r[1]), "=r"(r[2]), "=r"(r[3]) : "r"(addr));
}
__device__ __forceinline__ void mma16816(float* d, const uint32_t* a,
                                         uint32_t b0, uint32_t b1) {
    asm volatile(
        "mma.sync.aligned.m16n8k16.row.col.f32.f16.f16.f32 "
        "{%0,%1,%2,%3}, {%4,%5,%6,%7}, {%8,%9}, {%0,%1,%2,%3};"
        : "+f"(d[0]), "+f"(d[1]), "+f"(d[2]), "+f"(d[3])
        : "r"(a[0]), "r"(a[1]), "r"(a[2]), "r"(a[3]), "r"(b0), "r"(b1));
}
__device__ __forceinline__ unsigned pack2(float a, float b) {
    __half2 h = __halves2half2(__float2half_rn(a), __float2half_rn(b));
    return *reinterpret_cast<unsigned*>(&h);
}

// --------------------------------------------------------------------------
// Prep: one block per code k — fp16 convert + fp32 transpose + fp64 csq
// --------------------------------------------------------------------------
__global__ void conv_cent(const float* __restrict__ cent) {
    __shared__ double red[8];
    const int k = blockIdx.x;
    const int t = threadIdx.x;
    if (k == 0 && t == 0) g_count = 0;

    float f0 = cent[k * NC + t];
    float f1 = cent[k * NC + t + 256];
    g_c16[k * NC + t]        = __float2half_rn(f0);
    g_c16[k * NC + t + 256]  = __float2half_rn(f1);
    g_centT[t * NK + k]          = f0;
    g_centT[(t + 256) * NK + k]  = f1;

    double s = (double)f0 * f0 + (double)f1 * f1;
    #pragma unroll
    for (int d = 16; d > 0; d >>= 1)
        s += __shfl_xor_sync(0xFFFFFFFFu, s, d);
    if ((t & 31) == 0) red[t >> 5] = s;
    __syncthreads();
    if (t == 0) {
        double tot = 0.0;
        #pragma unroll
        for (int w = 0; w < 8; ++w) tot += red[w];
        g_csq[k] = (float)tot;
    }
}

// --------------------------------------------------------------------------
// Smem: 4 stages x 16 KB. Per stage: A [32 ch][128 px] fp16 = 8 KB (256 B
// rows, unit ^= row&7 swizzle), then B [128 codes][32 ch] = 8 KB (64 B rows,
// R10 swizzle). csq + top-2 scratch after the ring.
// --------------------------------------------------------------------------
#define STG_BYTES 16384
#define B_OFF     8192
#define OFF_CSQ   65536
#define OFF_K2    66048
#define OFF_V2    70144
#define SMEM_TOTAL 72192

// --------------------------------------------------------------------------
// Main GEMM: CTA = 128 px x 128 codes (grid 2048). A loaded fp32 from x's
// NATIVE layout (coalesced), converted in-kernel, consumed via ldmatrix.trans.
// B via cp.async. 16 iters of 32 channels, 4-buffer ring, 1 barrier/iter.
// --------------------------------------------------------------------------
__global__ __launch_bounds__(256, 2)
void hmma_top2(const float* __restrict__ x) {
    extern __shared__ __align__(1024) char smem[];
    const uint32_t sb = smem_u32(smem);
    const int tid  = threadIdx.x;
    const int lane = tid & 31;
    const int wid  = tid >> 5;
    const int wm   = wid >> 2;     // 0..1 : 64-px block
    const int wn   = wid & 3;      // 0..3 : 32-code block

    const int grp = blockIdx.x >> 2;
    const int kc  = blockIdx.x & 3;
    const int p0  = grp * 128;
    const int b   = p0 >> 12;
    const int hw0 = p0 & 4095;

    float* cs = (float*)(smem + OFF_CSQ);
    if (tid < 128) cs[tid] = g_csq[kc * 128 + tid];

    // ---- A-fill mapping: row = channel (0..31), jsel picks 16 px ----
    const int arow = tid & 31;
    const int jsel = tid >> 5;     // 0..7
    const float* xA = x + (size_t)b * NC * NHW + (size_t)arow * NHW + hw0 + jsel * 16;
    const uint32_t dA0 = sb + arow * 256 + (((2 * jsel)     ^ (arow & 7)) << 4);
    const uint32_t dA1 = sb + arow * 256 + (((2 * jsel + 1) ^ (arow & 7)) << 4);

    // ---- B loader: 2 x 16 B per thread per stage (R10 pattern) ----
    const int brow = tid >> 2;         // 0..63
    const int bj   = tid & 3;
    const char* srcB = (const char*)(g_c16 + (size_t)(kc * 128 + brow) * NC + bj * 8);
    const uint32_t dB = sb + B_OFF + brow * 64 + ((bj ^ ((brow >> 1) & 3)) << 4);
    // 2nd chunk: row += 64 -> src += 64*NC*2 bytes, dst += 64*64 bytes

    // ---- ldmatrix bases ----
    // A (trans): lane -> k-row (lane&7)+8*(lane>>4), m-half ((lane>>3)&1)
    const int krp = (lane & 7) + ((lane >> 4) << 3);
    const int mh  = (lane >> 3) & 1;
    uint32_t aT[4];
    #pragma unroll
    for (int mt = 0; mt < 4; ++mt)
        aT[mt] = sb + krp * 256 + (((wm * 8 + mt * 2 + mh) ^ (lane & 7)) << 4);
    // B (non-trans): R10 addressing
    const int rB  = wn * 32 + (lane & 15);
    const int swB = (rB >> 1) & 3;
    const int khalf = lane >> 4;
    uint32_t badr[2][2];
    #pragma unroll
    for (int ks = 0; ks < 2; ++ks) {
        const int jj = ks * 2 + khalf;
        #pragma unroll
        for (int nt = 0; nt < 2; ++nt)
            badr[ks][nt] = sb + B_OFF + (rB + nt * 16) * 64 + ((jj ^ swB) << 4);
    }

    float acc[4][4][4];
    #pragma unroll
    for (int m = 0; m < 4; ++m)
        #pragma unroll
        for (int n = 0; n < 4; ++n)
            #pragma unroll
            for (int r = 0; r < 4; ++r) acc[m][n][r] = 0.0f;

    float4 f[4];   // held x prefetch: 16 px of one channel
    auto ldg_x = [&](int i) {
        const float* s = xA + (size_t)i * 32 * NHW;
        f[0] = *(const float4*)(s);
        f[1] = *(const float4*)(s + 4);
        f[2] = *(const float4*)(s + 8);
        f[3] = *(const float4*)(s + 12);
    };
    auto sts_a = [&](int buf) {
        unsigned u0 = pack2(f[0].x, f[0].y), u1 = pack2(f[0].z, f[0].w);
        unsigned u2 = pack2(f[1].x, f[1].y), u3 = pack2(f[1].z, f[1].w);
        unsigned u4 = pack2(f[2].x, f[2].y), u5 = pack2(f[2].z, f[2].w);
        unsigned u6 = pack2(f[3].x, f[3].y), u7 = pack2(f[3].z, f[3].w);
        const uint32_t off = buf * STG_BYTES;
        asm volatile("st.shared.v4.b32 [%0], {%1,%2,%3,%4};"
                     :: "r"(dA0 + off), "r"(u0), "r"(u1), "r"(u2), "r"(u3) : "memory");
        asm volatile("st.shared.v4.b32 [%0], {%1,%2,%3,%4};"
                     :: "r"(dA1 + off), "r"(u4), "r"(u5), "r"(u6), "r"(u7) : "memory");
    };
    auto cpa_b = [&](int i) {
        const uint32_t off = (i & 3) * STG_BYTES;
        asm volatile("cp.async.cg.shared.global [%0], [%1], 16;"
            :: "r"(dB + off), "l"(srcB + (size_t)i * 64) : "memory");
        asm volatile("cp.async.cg.shared.global [%0], [%1], 16;"
            :: "r"(dB + 4096 + off), "l"(srcB + (size_t)64 * NC * 2 + (size_t)i * 64)
            : "memory");
        asm volatile("cp.async.commit_group;" ::: "memory");
    };

    // ---- prologue ----
    ldg_x(0);
    sts_a(0);
    cpa_b(0);
    ldg_x(1);
    cpa_b(1);
    cpa_b(2);

    #pragma unroll
    for (int i = 0; i < 16; ++i) {
        if (i < 14)       asm volatile("cp.async.wait_group 2;" ::: "memory");
        else if (i == 14) asm volatile("cp.async.wait_group 1;" ::: "memory");
        else              asm volatile("cp.async.wait_group 0;" ::: "memory");
        __syncthreads();               // A(i)+B(i) ready; compute i-1 done
        if (i + 1 < 16) {
            sts_a((i + 1) & 3);        // f holds stage i+1
            if (i + 2 < 16) ldg_x(i + 2);
        }
        if (i + 3 < 16) cpa_b(i + 3);

        const uint32_t S = (i & 3) * STG_BYTES;
        #pragma unroll
        for (int ks = 0; ks < 2; ++ks) {
            uint32_t ah[4][4];
            #pragma unroll
            for (int mt = 0; mt < 4; ++mt)
                ldmx4t(ah[mt], aT[mt] + S + ks * 4096);
            #pragma unroll
            for (int nt = 0; nt < 2; ++nt) {
                uint32_t bf[4];
                ldmx4(bf, badr[ks][nt] + S);
                #pragma unroll
                for (int sub = 0; sub < 2; ++sub) {
                    const int nn = nt * 2 + sub;
                    #pragma unroll
                    for (int mt = 0; mt < 4; ++mt)
                        mma16816(acc[mt][nn], ah[mt], bf[sub], bf[sub + 2]);
                }
            }
        }
    }

    // ---- epilogue: per-row top-2 in registers, merge via shfl + smem ----
    unsigned long long* smk = (unsigned long long*)(smem + OFF_K2);
    float*              smv = (float*)(smem + OFF_V2);
    const int r4 = lane >> 2, c2 = (lane & 3) << 1;

    #pragma unroll
    for (int mt = 0; mt < 4; ++mt) {
        unsigned long long k1a = ~0ULL, k1b = ~0ULL;
        float v2a = 3.0e38f, v2b = 3.0e38f;
        const int row = wm * 64 + mt * 16 + r4;
        #pragma unroll
        for (int nn = 0; nn < 4; ++nn) {
            #pragma unroll
            for (int cc = 0; cc < 2; ++cc) {
                const int col = wn * 32 + nn * 8 + c2 + cc;
                const int kg  = kc * 128 + col;
                float va = fmaf(-2.0f, acc[mt][nn][cc], cs[col]);
                float vb = fmaf(-2.0f, acc[mt][nn][cc + 2], cs[col]);
                unsigned long long ea = enc_key(va, kg);
                unsigned long long eb = enc_key(vb, kg);
                if (ea < k1a) { v2a = fminf(v2a, key_val(k1a)); k1a = ea; }
                else           v2a = fminf(v2a, va);
                if (eb < k1b) { v2b = fminf(v2b, key_val(k1b)); k1b = eb; }
                else           v2b = fminf(v2b, vb);
            }
        }
        #pragma unroll
        for (int d = 1; d <= 2; d <<= 1) {
            unsigned long long oka = __shfl_xor_sync(0xFFFFFFFFu, k1a, d);
            float ova              = __shfl_xor_sync(0xFFFFFFFFu, v2a, d);
            t2merge(k1a, v2a, oka, ova);
            unsigned long long okb = __shfl_xor_sync(0xFFFFFFFFu, k1b, d);
            float ovb              = __shfl_xor_sync(0xFFFFFFFFu, v2b, d);
            t2merge(k1b, v2b, okb, ovb);
        }
        if ((lane & 3) == 0) {
            smk[row * 4 + wn] = k1a;  smv[row * 4 + wn] = v2a;
            smk[(row + 8) * 4 + wn] = k1b;  smv[(row + 8) * 4 + wn] = v2b;
        }
    }
    __syncthreads();

    if (tid < 128) {
        unsigned long long k1 = smk[tid * 4];
        float v2 = smv[tid * 4];
        #pragma unroll
        for (int w = 1; w < 4; ++w) t2merge(k1, v2, smk[tid * 4 + w], smv[tid * 4 + w]);
        g_partk[(size_t)(p0 + tid) * 4 + kc] = k1;
        g_partv[(size_t)(p0 + tid) * 4 + kc] = v2;
    }
}

// --------------------------------------------------------------------------
// Finalize: global top-2 across chunks; enqueue tight margins for rescue.
// --------------------------------------------------------------------------
__global__ void finalize(float* __restrict__ out) {
    int p = blockIdx.x * 256 + threadIdx.x;
    unsigned long long k1 = g_partk[(size_t)p * 4];
    float v2 = g_partv[(size_t)p * 4];
    #pragma unroll
    for (int c = 1; c < 4; ++c)
        t2merge(k1, v2, g_partk[(size_t)p * 4 + c], g_partv[(size_t)p * 4 + c]);
    out[p] = (float)(int)(unsigned)(k1 & 0xFFFFFFFFULL);
    if (v2 - key_val(k1) < RESCUE_T) {
        int s = atomicAdd(&g_count, 1);
        g_queue[s] = p;
    }
}

// --------------------------------------------------------------------------
// Rescue: exact fp32 re-evaluation; 8 px/block batches, unrolled gather.
// --------------------------------------------------------------------------
__global__ __launch_bounds__(256, 2)
void rescue(const float* __restrict__ x, float* __restrict__ out) {
    __shared__ float xs[8][512];
    __shared__ unsigned long long best[8];
    const int t = threadIdx.x;
    const int cnt = g_count;

    for (int base = blockIdx.x * 8; base < cnt; base += 512 * 8) {
        const int nv = min(8, cnt - base);
        if (t < 8) best[t] = ~0ULL;
        #pragma unroll
        for (int i = 0; i < 8; ++i) {
            if (i < nv) {
                int p = g_queue[base + i];
                int b = p >> 12, hw = p & 4095;
                const float* src = x + (size_t)b * NC * NHW + hw;
                xs[i][t]       = src[(size_t)t * NHW];
                xs[i][t + 256] = src[(size_t)(t + 256) * NHW];
            }
        }
        __syncthreads();

        float a0[8], a1[8];
        #pragma unroll
        for (int i = 0; i < 8; ++i) { a0[i] = 0.0f; a1[i] = 0.0f; }
        const float cq0 = g_csq[t], cq1 = g_csq[t + 256];

        #pragma unroll 4
        for (int cc = 0; cc < 512; ++cc) {
            float c0v = g_centT[cc * NK + t];
            float c1v = g_centT[cc * NK + t + 256];
            #pragma unroll
            for (int i = 0; i < 8; ++i) {
                float xv = xs[i][cc];
                a0[i] = fmaf(xv, c0v, a0[i]);
                a1[i] = fmaf(xv, c1v, a1[i]);
            }
        }
        #pragma unroll
        for (int i = 0; i < 8; ++i) {
            if (i < nv) {
                unsigned long long e0 = enc_key(fmaf(-2.0f, a0[i], cq0), t);
                unsigned long long e1 = enc_key(fmaf(-2.0f, a1[i], cq1), t + 256);
                atomicMin(&best[i], e0 < e1 ? e0 : e1);
            }
        }
        __syncthreads();
        if (t < nv)
            out[g_queue[base + t]] =
                (float)(int)(unsigned)(best[t] & 0xFFFFFFFFULL);
        __syncthreads();
    }
}

// --------------------------------------------------------------------------
// Launch
// --------------------------------------------------------------------------
extern "C" void kernel_launch(void* const* d_in, const int* in_sizes, int n_in,
                              void* d_out, int out_size) {
    const float* x    = (const float*)d_in[0];
    const float* cent = (const float*)d_in[1];
    if (n_in >= 2 && in_sizes[0] < in_sizes[1]) {
        const float* t = x; x = cent; cent = t;
    }

    cudaFuncSetAttribute(hmma_top2,
                         cudaFuncAttributeMaxDynamicSharedMemorySize, SMEM_TOTAL);

    conv_cent<<<NK, 256>>>(cent);
    hmma_top2<<<NP / 128 * 4, 256, SMEM_TOTAL>>>(x);
    finalize<<<NP / 256, 256>>>((float*)d_out);
    rescue<<<512, 256>>>(x, (float*)d_out);
    (void)out_size;
}

// round 15
// speedup vs baseline: 1.5745x; 1.5745x over previous
#include <cuda_runtime.h>
#include <cuda_fp16.h>
#include <cstdint>

#define NB  16
#define NC  512
#define NK  512
#define NHW 4096
#define NP  (NB * NHW)   // 65536 pixels

#define RESCUE_T 0.2f

// --------------------------------------------------------------------------
// Allocation-free scratch
// --------------------------------------------------------------------------
__device__ __half g_x16[(size_t)NP * NC];   // x fp16, [p][c] K-major
__device__ __half g_c16[NK * NC];           // centers fp16 [k][c]
__device__ float  g_centT[NC * NK];         // centers fp32 transposed [c][k]
__device__ float  g_csq[NK];
__device__ unsigned long long g_partk[(size_t)NP * 4];
__device__ float              g_partv[(size_t)NP * 4];
__device__ int g_count;
__device__ int g_queue[NP];

// --------------------------------------------------------------------------
// Helpers
// --------------------------------------------------------------------------
__device__ __forceinline__ uint32_t smem_u32(const void* p) {
    uint32_t a;
    asm("{ .reg .u64 t; cvta.to.shared.u64 t, %1; cvt.u32.u64 %0, t; }"
        : "=r"(a) : "l"(p));
    return a;
}
__device__ __forceinline__ unsigned long long enc_key(float v, int k) {
    unsigned u = __float_as_uint(v);
    u = (u & 0x80000000u) ? ~u : (u | 0x80000000u);
    return ((unsigned long long)u << 32) | (unsigned)k;
}
__device__ __forceinline__ float key_val(unsigned long long key) {
    unsigned u = (unsigned)(key >> 32);
    unsigned b = (u & 0x80000000u) ? (u & 0x7FFFFFFFu) : ~u;
    return __uint_as_float(b);
}
__device__ __forceinline__ void t2merge(unsigned long long& k1, float& v2,
                                        unsigned long long ok1, float ov2) {
    if (ok1 < k1) { v2 = fminf(key_val(k1), ov2); k1 = ok1; }
    else          { v2 = fminf(v2, key_val(ok1)); }
}
__device__ __forceinline__ void ldmx4(uint32_t* r, uint32_t addr) {
    asm volatile("ldmatrix.sync.aligned.m8n8.x4.shared.b16 {%0,%1,%2,%3}, [%4];"
                 : "=r"(r[0]), "=r"(r[1]), "=r"(r[2]), "=r"(r[3]) : "r"(addr));
}
__device__ __forceinline__ void mma16816(float* d, const uint32_t* a,
                                         uint32_t b0, uint32_t b1) {
    asm volatile(
        "mma.sync.aligned.m16n8k16.row.col.f32.f16.f16.f32 "
        "{%0,%1,%2,%3}, {%4,%5,%6,%7}, {%8,%9}, {%0,%1,%2,%3};"
        : "+f"(d[0]), "+f"(d[1]), "+f"(d[2]), "+f"(d[3])
        : "r"(a[0]), "r"(a[1]), "r"(a[2]), "r"(a[3]), "r"(b0), "r"(b1));
}

// --------------------------------------------------------------------------
// Prep: one block per code k — fp16 convert + fp32 transpose + fp64 csq
// --------------------------------------------------------------------------
__global__ void conv_cent(const float* __restrict__ cent) {
    __shared__ double red[8];
    const int k = blockIdx.x;
    const int t = threadIdx.x;
    if (k == 0 && t == 0) g_count = 0;

    float f0 = cent[k * NC + t];
    float f1 = cent[k * NC + t + 256];
    g_c16[k * NC + t]        = __float2half_rn(f0);
    g_c16[k * NC + t + 256]  = __float2half_rn(f1);
    g_centT[t * NK + k]          = f0;
    g_centT[(t + 256) * NK + k]  = f1;

    double s = (double)f0 * f0 + (double)f1 * f1;
    #pragma unroll
    for (int d = 16; d > 0; d >>= 1)
        s += __shfl_xor_sync(0xFFFFFFFFu, s, d);
    if ((t & 31) == 0) red[t >> 5] = s;
    __syncthreads();
    if (t == 0) {
        double tot = 0.0;
        #pragma unroll
        for (int w = 0; w < 8; ++w) tot += red[w];
        g_csq[k] = (float)tot;
    }
}

// x (B,C,H,W) fp32 -> [p][c] fp16 via smem transpose; coalesced writes
__global__ void convert_x(const float* __restrict__ x) {
    __shared__ float s[64][65];
    const int p0 = blockIdx.x * 64;
    const int c0 = blockIdx.y * 64;
    const int b   = p0 >> 12;
    const int hw0 = p0 & 4095;
    const int t = threadIdx.x;
    const float* src = x + (size_t)b * NC * NHW + hw0;

    #pragma unroll
    for (int i = 0; i < 4; ++i) {
        int cl = i * 16 + (t >> 4);
        int pl = (t & 15) * 4;
        float4 v = *reinterpret_cast<const float4*>(src + (size_t)(c0 + cl) * NHW + pl);
        s[cl][pl] = v.x; s[cl][pl + 1] = v.y; s[cl][pl + 2] = v.z; s[cl][pl + 3] = v.w;
    }
    __syncthreads();

    {
        const int pl  = t >> 2;
        const int c16 = (t & 3) << 4;
        unsigned u[8];
        #pragma unroll
        for (int j = 0; j < 8; ++j) {
            __half2 h = __halves2half2(__float2half_rn(s[c16 + j * 2][pl]),
                                       __float2half_rn(s[c16 + j * 2 + 1][pl]));
            u[j] = *reinterpret_cast<unsigned*>(&h);
        }
        __half* dst = &g_x16[(size_t)(p0 + pl) * NC + c0 + c16];
        *reinterpret_cast<uint4*>(dst)     = make_uint4(u[0], u[1], u[2], u[3]);
        *reinterpret_cast<uint4*>(dst + 8) = make_uint4(u[4], u[5], u[6], u[7]);
    }
}

// --------------------------------------------------------------------------
// Smem: 3 stages x 32 KB (A 16 KB + B 16 KB), 128 B rows, XOR swizzle on
// 16 B units (j ^= row&7). csq after stages; top-2 scratch overlays stage 0.
// --------------------------------------------------------------------------
#define STG_BYTES 32768
#define B_OFF     16384
#define OFF_CSQ   98304
#define SMEM_TOTAL 98816

// --------------------------------------------------------------------------
// Main GEMM — identical to R13 (known ~106 us).
// --------------------------------------------------------------------------
__global__ __launch_bounds__(256, 2)
void hmma_top2() {
    extern __shared__ __align__(1024) char smem[];
    const uint32_t sb = smem_u32(smem);
    const int tid  = threadIdx.x;
    const int lane = tid & 31;
    const int wid  = tid >> 5;
    const int wm   = wid >> 2;
    const int wn   = wid & 3;

    const int grp = blockIdx.x >> 2;
    const int kc  = blockIdx.x & 3;
    const int p0  = grp * 128;

    float* cs = (float*)(smem + OFF_CSQ);
    if (tid < 128) cs[tid] = g_csq[kc * 128 + tid];

    const int row0 = tid >> 3;
    const int j8   = tid & 7;
    const char* srcA = (const char*)(g_x16 + (size_t)(p0 + row0) * NC + j8 * 8);
    const char* srcB = (const char*)(g_c16 + (size_t)(kc * 128 + row0) * NC + j8 * 8);
    const uint32_t dstA = sb + row0 * 128 + ((j8 ^ (row0 & 7)) << 4);
    const uint32_t dstB = dstA + B_OFF;

    const int rA  = wm * 64 + (lane & 15);
    const int swA = rA & 7;
    const int rB  = wn * 32 + (lane & 15);
    const int swB = rB & 7;
    const int khalf = lane >> 4;
    uint32_t aBase[4], bBase[2], xorA[4], xorB[4];
    #pragma unroll
    for (int mt = 0; mt < 4; ++mt) aBase[mt] = sb + (rA + mt * 16) * 128;
    #pragma unroll
    for (int nt = 0; nt < 2; ++nt) bBase[nt] = sb + B_OFF + (rB + nt * 16) * 128;
    #pragma unroll
    for (int ks = 0; ks < 4; ++ks) {
        const int jj = ks * 2 + khalf;
        xorA[ks] = (uint32_t)((jj ^ swA) << 4);
        xorB[ks] = (uint32_t)((jj ^ swB) << 4);
    }

    float acc[4][4][4];
    #pragma unroll
    for (int m = 0; m < 4; ++m)
        #pragma unroll
        for (int n = 0; n < 4; ++n)
            #pragma unroll
            for (int r = 0; r < 4; ++r) acc[m][n][r] = 0.0f;

    #pragma unroll
    for (int i = 0; i < 2; ++i) {
        #pragma unroll
        for (int u = 0; u < 4; ++u) {
            asm volatile("cp.async.cg.shared.global [%0], [%1], 16;"
                :: "r"(dstA + u * 4096 + i * STG_BYTES),
                   "l"(srcA + (size_t)u * 32 * NC * 2 + i * 128) : "memory");
            asm volatile("cp.async.cg.shared.global [%0], [%1], 16;"
                :: "r"(dstB + u * 4096 + i * STG_BYTES),
                   "l"(srcB + (size_t)u * 32 * NC * 2 + i * 128) : "memory");
        }
        asm volatile("cp.async.commit_group;" ::: "memory");
    }

    #pragma unroll
    for (int i = 0; i < 8; ++i) {
        if (i < 7) asm volatile("cp.async.wait_group 1;" ::: "memory");
        else       asm volatile("cp.async.wait_group 0;" ::: "memory");
        __syncthreads();
        if (i + 2 < 8) {
            const uint32_t SD = ((i + 2) % 3) * STG_BYTES;
            #pragma unroll
            for (int u = 0; u < 4; ++u) {
                asm volatile("cp.async.cg.shared.global [%0], [%1], 16;"
                    :: "r"(dstA + u * 4096 + SD),
                       "l"(srcA + (size_t)u * 32 * NC * 2 + (i + 2) * 128) : "memory");
                asm volatile("cp.async.cg.shared.global [%0], [%1], 16;"
                    :: "r"(dstB + u * 4096 + SD),
                       "l"(srcB + (size_t)u * 32 * NC * 2 + (i + 2) * 128) : "memory");
            }
            asm volatile("cp.async.commit_group;" ::: "memory");
        }
        const uint32_t S = (i % 3) * STG_BYTES;
        #pragma unroll
        for (int ks = 0; ks < 4; ++ks) {
            uint32_t ah[4][4];
            #pragma unroll
            for (int mt = 0; mt < 4; ++mt)
                ldmx4(ah[mt], aBase[mt] + S + xorA[ks]);
            #pragma unroll
            for (int nt = 0; nt < 2; ++nt) {
                uint32_t bf[4];
                ldmx4(bf, bBase[nt] + S + xorB[ks]);
                #pragma unroll
                for (int sub = 0; sub < 2; ++sub) {
                    const int nn = nt * 2 + sub;
                    #pragma unroll
                    for (int mt = 0; mt < 4; ++mt)
                        mma16816(acc[mt][nn], ah[mt], bf[sub], bf[sub + 2]);
                }
            }
        }
    }
    __syncthreads();

    unsigned long long* smk = (unsigned long long*)smem;
    float*              smv = (float*)(smem + 4096);
    const int r4 = lane >> 2, c2 = (lane & 3) << 1;

    #pragma unroll
    for (int mt = 0; mt < 4; ++mt) {
        unsigned long long k1a = ~0ULL, k1b = ~0ULL;
        float v2a = 3.0e38f, v2b = 3.0e38f;
        const int row = wm * 64 + mt * 16 + r4;
        #pragma unroll
        for (int nn = 0; nn < 4; ++nn) {
            #pragma unroll
            for (int cc = 0; cc < 2; ++cc) {
                const int col = wn * 32 + nn * 8 + c2 + cc;
                const int kg  = kc * 128 + col;
                float va = fmaf(-2.0f, acc[mt][nn][cc], cs[col]);
                float vb = fmaf(-2.0f, acc[mt][nn][cc + 2], cs[col]);
                unsigned long long ea = enc_key(va, kg);
                unsigned long long eb = enc_key(vb, kg);
                if (ea < k1a) { v2a = fminf(v2a, key_val(k1a)); k1a = ea; }
                else           v2a = fminf(v2a, va);
                if (eb < k1b) { v2b = fminf(v2b, key_val(k1b)); k1b = eb; }
                else           v2b = fminf(v2b, vb);
            }
        }
        #pragma unroll
        for (int d = 1; d <= 2; d <<= 1) {
            unsigned long long oka = __shfl_xor_sync(0xFFFFFFFFu, k1a, d);
            float ova              = __shfl_xor_sync(0xFFFFFFFFu, v2a, d);
            t2merge(k1a, v2a, oka, ova);
            unsigned long long okb = __shfl_xor_sync(0xFFFFFFFFu, k1b, d);
            float ovb              = __shfl_xor_sync(0xFFFFFFFFu, v2b, d);
            t2merge(k1b, v2b, okb, ovb);
        }
        if ((lane & 3) == 0) {
            smk[row * 4 + wn] = k1a;  smv[row * 4 + wn] = v2a;
            smk[(row + 8) * 4 + wn] = k1b;  smv[(row + 8) * 4 + wn] = v2b;
        }
    }
    __syncthreads();

    if (tid < 128) {
        unsigned long long k1 = smk[tid * 4];
        float v2 = smv[tid * 4];
        #pragma unroll
        for (int w = 1; w < 4; ++w) t2merge(k1, v2, smk[tid * 4 + w], smv[tid * 4 + w]);
        g_partk[(size_t)(p0 + tid) * 4 + kc] = k1;
        g_partv[(size_t)(p0 + tid) * 4 + kc] = v2;
    }
}

// --------------------------------------------------------------------------
// Finalize: global top-2; write approx answer; enqueue tight margins and
// reset the pixel's g_partk[p*4] slot for rescue's cross-block atomicMin.
// --------------------------------------------------------------------------
__global__ void finalize(float* __restrict__ out) {
    int p = blockIdx.x * 256 + threadIdx.x;
    unsigned long long k1 = g_partk[(size_t)p * 4];
    float v2 = g_partv[(size_t)p * 4];
    #pragma unroll
    for (int c = 1; c < 4; ++c)
        t2merge(k1, v2, g_partk[(size_t)p * 4 + c], g_partv[(size_t)p * 4 + c]);
    out[p] = (float)(int)(unsigned)(k1 & 0xFFFFFFFFULL);
    if (v2 - key_val(k1) < RESCUE_T) {
        int s = atomicAdd(&g_count, 1);
        g_queue[s] = p;
        g_partk[(size_t)p * 4] = ~0ULL;   // slot for rescue's atomicMin
    }
}

// --------------------------------------------------------------------------
// Rescue: exact fp32 re-evaluation, parallelized 4x by code quarter.
// Block = 8 pixels x 128 codes; channel halves split across threads.
// Per-pixel result accumulated via global atomicMin on g_partk[p*4].
// --------------------------------------------------------------------------
__global__ __launch_bounds__(256, 4)
void rescue(const float* __restrict__ x) {
    __shared__ float xs[8][512];
    __shared__ float pp[128][8];
    __shared__ unsigned long long best[8];
    const int t    = threadIdx.x;
    const int lane = t & 31;
    const int cnt  = g_count;

    for (int blk = blockIdx.x; ; blk += gridDim.x) {
        const int base = (blk >> 2) * 8;
        if (base >= cnt) break;
        const int q  = blk & 3;
        const int nv = min(8, cnt - base);

        if (t < 8) best[t] = ~0ULL;
        #pragma unroll
        for (int i = 0; i < 8; ++i) {
            if (i < nv) {
                int p = g_queue[base + i];
                const float* src = x + (size_t)(p >> 12) * NC * NHW + (p & 4095);
                xs[i][t]       = src[(size_t)t * NHW];
                xs[i][t + 256] = src[(size_t)(t + 256) * NHW];
            }
        }
        __syncthreads();

        const int kl  = t & 127;
        const int kg  = q * 128 + kl;
        const int ch0 = (t >> 7) << 8;   // 0 or 256
        float a[8];
        #pragma unroll
        for (int i = 0; i < 8; ++i) a[i] = 0.0f;
        const float* cr = g_centT + (size_t)ch0 * NK + kg;
        #pragma unroll 4
        for (int cc = 0; cc < 256; ++cc) {
            float cv = cr[(size_t)cc * NK];
            #pragma unroll
            for (int i = 0; i < 8; ++i)
                a[i] = fmaf(xs[i][ch0 + cc], cv, a[i]);
        }
        // combine channel halves: upper half posts partials
        if (t >= 128) {
            #pragma unroll
            for (int i = 0; i < 8; ++i) pp[kl][i] = a[i];
        }
        __syncthreads();
        if (t < 128) {
            const float cq = g_csq[kg];
            #pragma unroll
            for (int i = 0; i < 8; ++i) {
                float dot = a[i] + pp[kl][i];
                unsigned long long key = enc_key(fmaf(-2.0f, dot, cq), kg);
                #pragma unroll
                for (int d = 16; d > 0; d >>= 1) {
                    unsigned long long o = __shfl_xor_sync(0xFFFFFFFFu, key, d);
                    if (o < key) key = o;
                }
                if (lane == 0 && i < nv) atomicMin(&best[i], key);
            }
        }
        __syncthreads();
        if (t < nv)
            atomicMin(&g_partk[(size_t)g_queue[base + t] * 4], best[t]);
        __syncthreads();
    }
}

// --------------------------------------------------------------------------
// Rescue write-back: queued pixels get their exact argmin.
// --------------------------------------------------------------------------
__global__ void rescue_write(float* __restrict__ out) {
    int i = blockIdx.x * 256 + threadIdx.x;
    if (i < g_count) {
        int p = g_queue[i];
        out[p] = (float)(int)(unsigned)(g_partk[(size_t)p * 4] & 0xFFFFFFFFULL);
    }
}

// --------------------------------------------------------------------------
// Launch
// --------------------------------------------------------------------------
extern "C" void kernel_launch(void* const* d_in, const int* in_sizes, int n_in,
                              void* d_out, int out_size) {
    const float* x    = (const float*)d_in[0];
    const float* cent = (const float*)d_in[1];
    if (n_in >= 2 && in_sizes[0] < in_sizes[1]) {
        const float* t = x; x = cent; cent = t;
    }

    cudaFuncSetAttribute(hmma_top2,
                         cudaFuncAttributeMaxDynamicSharedMemorySize, SMEM_TOTAL);

    conv_cent<<<NK, 256>>>(cent);
    dim3 tg(NP / 64, NC / 64);
    convert_x<<<tg, 256>>>(x);
    hmma_top2<<<NP / 128 * 4, 256, SMEM_TOTAL>>>();
    finalize<<<NP / 256, 256>>>((float*)d_out);
    rescue<<<2048, 256>>>(x);
    rescue_write<<<NP / 256, 256>>>((float*)d_out);
    (void)out_size;
}